// round 1
// baseline (speedup 1.0000x reference)
#include <cuda_runtime.h>
#include <cuda_bf16.h>
#include <math.h>

// Problem constants
#define Bz 8
#define Nn 1024
#define Dd 256
#define Hh 8
#define HC 4
#define DH 64
#define HD 2048                 // Hh*Dd
#define ND (Nn*Dd)              // 262144
#define NNt ((size_t)Nn*Nn)     // 1048576

// ---------------- scratch (device globals; no runtime allocation) ----------------
__device__ float g_posq[Bz*Dd];
__device__ float g_w[Bz*Dd];
__device__ float g_sel[Bz*Nn];
__device__ float g_fa[Bz*ND];
__device__ float g_connect[(size_t)Bz*Nn*Nn];          // 32 MB
__device__ float g_Wh[(size_t)Bz*Hh*ND];               // 64 MB
__device__ float g_s1[Bz*Hh*Nn];
__device__ float g_s2[Bz*Hh*Nn];
__device__ float g_attn[(size_t)Bz*Hh*Nn*Nn];          // 256 MB (reused for CA logits)
__device__ float g_cat[(size_t)Bz*Nn*HD];              // 64 MB
__device__ float g_Who[Bz*ND];
__device__ float g_so1[Bz*Nn];
__device__ float g_so2[Bz*Nn];
__device__ float g_attno[(size_t)Bz*Nn*Nn];            // 32 MB
__device__ float g_gout[Bz*ND];
__device__ float g_qx[Bz*ND];
__device__ float g_kv[Bz*ND];
__device__ float g_q[Bz*ND];
__device__ float g_k[Bz*ND];
__device__ float g_v[Bz*ND];
__device__ float g_o[Bz*ND];

// ---------------- generic tiled fp32 GEMM ----------------
// C = A @ B (or A @ B^T when TB). All dims assumed multiples of tile sizes.
// Batched via blockIdx.z with offset = (z/zInner)*s?b + (z%zInner)*s?i.
#define BM 64
#define BN 64
#define BK 16

enum { EPI_NONE = 0, EPI_ELU = 1, EPI_CONNECT = 2, EPI_RESID = 3 };

template <bool TB>
__global__ void __launch_bounds__(256)
gemm_k(const float* __restrict__ A, const float* __restrict__ Bm, float* __restrict__ C,
       int M, int Nc, int K, int lda, int ldb, int ldc,
       int zInner,
       long sAb, long sAi, long sBb, long sBi, long sCb, long sCi,
       int epi, const float* __restrict__ e1, long sE1b, const float* __restrict__ e2)
{
    __shared__ float As[BK][BM + 4];
    __shared__ float Bs[BK][BN + 4];

    int z  = blockIdx.z;
    int zb = z / zInner, zi = z % zInner;
    const float* Ap = A  + (size_t)zb * sAb + (size_t)zi * sAi;
    const float* Bp = Bm + (size_t)zb * sBb + (size_t)zi * sBi;
    float*       Cp = C  + (size_t)zb * sCb + (size_t)zi * sCi;
    const float* e1p = e1 ? (e1 + (size_t)zb * sE1b) : nullptr;

    int m0 = blockIdx.y * BM;
    int n0 = blockIdx.x * BN;
    int tid = threadIdx.x;
    int tx = tid & 15, ty = tid >> 4;

    float acc[4][4] = {};

    for (int k0 = 0; k0 < K; k0 += BK) {
        #pragma unroll
        for (int l = 0; l < 4; l++) {
            int idx = tid + l * 256;
            int i  = idx >> 4;
            int kk = idx & 15;
            As[kk][i] = Ap[(size_t)(m0 + i) * lda + k0 + kk];
        }
        #pragma unroll
        for (int l = 0; l < 4; l++) {
            int idx = tid + l * 256;
            if (TB) {
                int j  = idx >> 4;
                int kk = idx & 15;
                Bs[kk][j] = Bp[(size_t)(n0 + j) * ldb + k0 + kk];
            } else {
                int kk = idx >> 6;
                int j  = idx & 63;
                Bs[kk][j] = Bp[(size_t)(k0 + kk) * ldb + n0 + j];
            }
        }
        __syncthreads();
        #pragma unroll
        for (int kk = 0; kk < BK; kk++) {
            float4 av = *reinterpret_cast<const float4*>(&As[kk][ty * 4]);
            float4 bv = *reinterpret_cast<const float4*>(&Bs[kk][tx * 4]);
            float a[4] = {av.x, av.y, av.z, av.w};
            float b[4] = {bv.x, bv.y, bv.z, bv.w};
            #pragma unroll
            for (int r = 0; r < 4; r++)
                #pragma unroll
                for (int c = 0; c < 4; c++)
                    acc[r][c] += a[r] * b[c];
        }
        __syncthreads();
    }

    #pragma unroll
    for (int r = 0; r < 4; r++) {
        int cm = m0 + ty * 4 + r;
        size_t rowoff = (size_t)cm * ldc + n0 + tx * 4;
        float4 outv;
        float* ov = reinterpret_cast<float*>(&outv);
        #pragma unroll
        for (int c = 0; c < 4; c++) {
            int cn = n0 + tx * 4 + c;
            float v = acc[r][c];
            if (epi == EPI_NONE) {
                ov[c] = v;
            } else if (epi == EPI_ELU) {
                ov[c] = v > 0.f ? v : expm1f(v);
            } else if (epi == EPI_CONNECT) {
                ov[c] = (v > 0.f && e1p[cm] > 0.5f && e1p[cn] > 0.5f) ? 1.f : 0.f;
            } else { // EPI_RESID: out = X + gamma[cn] * v
                ov[c] = e1p[rowoff + c] + e2[cn] * v;
            }
        }
        *reinterpret_cast<float4*>(&Cp[rowoff]) = outv;
    }
}

// ---------------- auxiliary kernels ----------------

// pos_query[b,d] = masked mean of x over tokens with mask==1
__global__ void k_posquery(const float* __restrict__ x, const int* __restrict__ mask,
                           float* __restrict__ pq)
{
    int b = blockIdx.x, d = threadIdx.x;
    float s = 0.f, cnt = 0.f;
    for (int n = 0; n < Nn; n++) {
        int m = mask[b * Nn + n];
        if (m == 1) { s += x[((size_t)b * Nn + n) * Dd + d]; cnt += 1.f; }
    }
    pq[b * Dd + d] = s / fmaxf(cnt, 1.f);
}

// w[b] = sim_Wx @ (pos_query[b] @ sim_Wq)
__global__ void k_simvec(const float* __restrict__ Wx, const float* __restrict__ Wq,
                         const float* __restrict__ pq, float* __restrict__ w)
{
    __shared__ float spq[Dd];
    __shared__ float qs[Dd];
    int b = blockIdx.x, t = threadIdx.x;
    spq[t] = pq[b * Dd + t];
    __syncthreads();
    float a = 0.f;
    for (int i = 0; i < Dd; i++) a += spq[i] * Wq[i * Dd + t];
    qs[t] = a;
    __syncthreads();
    float a2 = 0.f;
    for (int j = 0; j < Dd; j++) a2 += Wx[t * Dd + j] * qs[j];
    w[b * Dd + t] = a2;
}

// pos_sim[b,n] = sigmoid(dot(x[b,n], w[b]) / 16); sel = pos_sim > 0.97
__global__ void k_possim(const float* __restrict__ x, const float* __restrict__ w,
                         float* __restrict__ possim_out, float* __restrict__ sel)
{
    int row = blockIdx.x * 8 + (threadIdx.x >> 5);
    int lane = threadIdx.x & 31;
    int b = row / Nn;
    float s = 0.f;
    for (int e = lane; e < Dd; e += 32) s += x[(size_t)row * Dd + e] * w[b * Dd + e];
    #pragma unroll
    for (int o = 16; o; o >>= 1) s += __shfl_xor_sync(0xffffffffu, s, o);
    if (lane == 0) {
        float p = 1.f / (1.f + expf(-s * 0.0625f));
        possim_out[row] = p;
        sel[row] = (p > 0.97f) ? 1.f : 0.f;
    }
}

// s1[row]=dot(rows[row], a1[head]), s2 likewise.  head = (row / N) % nheads
__global__ void k_dot2(const float* __restrict__ rows, const float* __restrict__ a1,
                       const float* __restrict__ a2, float* __restrict__ s1,
                       float* __restrict__ s2, int nheads)
{
    int row = blockIdx.x * 8 + (threadIdx.x >> 5);
    int lane = threadIdx.x & 31;
    int head = (row / Nn) % nheads;
    const float* rp = rows + (size_t)row * Dd;
    const float* a1p = a1 + head * Dd;
    const float* a2p = a2 + head * Dd;
    float u = 0.f, v = 0.f;
    for (int e = lane; e < Dd; e += 32) {
        float rv = rp[e];
        u += rv * a1p[e];
        v += rv * a2p[e];
    }
    #pragma unroll
    for (int o = 16; o; o >>= 1) {
        u += __shfl_xor_sync(0xffffffffu, u, o);
        v += __shfl_xor_sync(0xffffffffu, v, o);
    }
    if (lane == 0) { s1[row] = u; s2[row] = v; }
}

// GAT-style masked softmax:  attn[z,i,:] = softmax_j( connect ? leaky(s1+s2) : -9e15 )
__global__ void k_softmax_gat(const float* __restrict__ s1, const float* __restrict__ s2,
                              const float* __restrict__ connect, float* __restrict__ attn,
                              int nheads)
{
    __shared__ float red[256];
    int i = blockIdx.x;
    int z = blockIdx.y;
    int b = z / nheads;
    const float* con = connect + (size_t)b * NNt + (size_t)i * Nn;
    const float* s2p = s2 + (size_t)z * Nn;
    float s1v = s1[(size_t)z * Nn + i];
    int t = threadIdx.x;
    float v[4];
    float mx = -INFINITY;
    #pragma unroll
    for (int k = 0; k < 4; k++) {
        int j = t + k * 256;
        float e = s1v + s2p[j];
        e = (e >= 0.f) ? e : 0.2f * e;
        v[k] = (con[j] > 0.5f) ? e : -9.0e15f;
        mx = fmaxf(mx, v[k]);
    }
    red[t] = mx; __syncthreads();
    for (int s = 128; s > 0; s >>= 1) { if (t < s) red[t] = fmaxf(red[t], red[t + s]); __syncthreads(); }
    mx = red[0]; __syncthreads();
    float sum = 0.f;
    #pragma unroll
    for (int k = 0; k < 4; k++) { v[k] = expf(v[k] - mx); sum += v[k]; }
    red[t] = sum; __syncthreads();
    for (int s = 128; s > 0; s >>= 1) { if (t < s) red[t] += red[t + s]; __syncthreads(); }
    float inv = 1.f / red[0];
    float* out = attn + (size_t)z * NNt + (size_t)i * Nn;
    #pragma unroll
    for (int k = 0; k < 4; k++) out[t + k * 256] = v[k] * inv;
}

// Cross-attention masked softmax (in place over logits buffer), scale=0.125
__global__ void k_softmax_ca(float* __restrict__ logits, const float* __restrict__ sel)
{
    __shared__ float red[256];
    int i = blockIdx.x;
    int z = blockIdx.y;          // b*HC + hc
    int b = z / HC;
    float* row = logits + (size_t)z * NNt + (size_t)i * Nn;
    const float* sp = sel + b * Nn;
    int t = threadIdx.x;
    float v[4];
    float mx = -INFINITY;
    #pragma unroll
    for (int k = 0; k < 4; k++) {
        int j = t + k * 256;
        v[k] = (sp[j] > 0.5f) ? row[j] * 0.125f : -1.0e9f;
        mx = fmaxf(mx, v[k]);
    }
    red[t] = mx; __syncthreads();
    for (int s = 128; s > 0; s >>= 1) { if (t < s) red[t] = fmaxf(red[t], red[t + s]); __syncthreads(); }
    mx = red[0]; __syncthreads();
    float sum = 0.f;
    #pragma unroll
    for (int k = 0; k < 4; k++) { v[k] = expf(v[k] - mx); sum += v[k]; }
    red[t] = sum; __syncthreads();
    for (int s = 128; s > 0; s >>= 1) { if (t < s) red[t] += red[t + s]; __syncthreads(); }
    float inv = 1.f / red[0];
    #pragma unroll
    for (int k = 0; k < 4; k++) row[t + k * 256] = v[k] * inv;
}

// LayerNorm (biased variance), warp per row
__global__ void k_ln(const float* __restrict__ in, const float* __restrict__ g,
                     const float* __restrict__ bb, float* __restrict__ out)
{
    int row = blockIdx.x * 8 + (threadIdx.x >> 5);
    int lane = threadIdx.x & 31;
    size_t base = (size_t)row * Dd;
    float vbuf[8];
    float s = 0.f, sq = 0.f;
    #pragma unroll
    for (int k = 0; k < 8; k++) {
        float x = in[base + lane + k * 32];
        vbuf[k] = x; s += x; sq += x * x;
    }
    #pragma unroll
    for (int o = 16; o; o >>= 1) {
        s += __shfl_xor_sync(0xffffffffu, s, o);
        sq += __shfl_xor_sync(0xffffffffu, sq, o);
    }
    float mean = s * (1.f / Dd);
    float var = sq * (1.f / Dd) - mean * mean;
    float rstd = rsqrtf(var + 1e-5f);
    #pragma unroll
    for (int k = 0; k < 8; k++) {
        int d = lane + k * 32;
        out[base + d] = (vbuf[k] - mean) * rstd * g[d] + bb[d];
    }
}

// kv = LN4( sel ? gout + pos_emb : 0 )
__global__ void k_qfull_ln(const float* __restrict__ gout, const float* __restrict__ pe,
                           const float* __restrict__ sel, const float* __restrict__ g,
                           const float* __restrict__ bb, float* __restrict__ out)
{
    int row = blockIdx.x * 8 + (threadIdx.x >> 5);
    int lane = threadIdx.x & 31;
    int n = row % Nn;
    size_t base = (size_t)row * Dd;
    float selv = sel[row];
    float vbuf[8];
    float s = 0.f, sq = 0.f;
    #pragma unroll
    for (int k = 0; k < 8; k++) {
        int d = lane + k * 32;
        float x = (selv > 0.5f) ? (gout[base + d] + pe[(size_t)n * Dd + d]) : 0.f;
        vbuf[k] = x; s += x; sq += x * x;
    }
    #pragma unroll
    for (int o = 16; o; o >>= 1) {
        s += __shfl_xor_sync(0xffffffffu, s, o);
        sq += __shfl_xor_sync(0xffffffffu, sq, o);
    }
    float mean = s * (1.f / Dd);
    float var = sq * (1.f / Dd) - mean * mean;
    float rstd = rsqrtf(var + 1e-5f);
    #pragma unroll
    for (int k = 0; k < 8; k++) {
        int d = lane + k * 32;
        out[base + d] = (vbuf[k] - mean) * rstd * g[d] + bb[d];
    }
}

// ---------------- launch ----------------
#define GETSYM(p, s) do { void* _t; cudaGetSymbolAddress(&_t, s); p = (float*)_t; } while (0)

extern "C" void kernel_launch(void* const* d_in, const int* in_sizes, int n_in,
                              void* d_out, int out_size)
{
    const float* x      = (const float*)d_in[0];
    const int*   mask   = (const int*)  d_in[1];
    const float* pe     = (const float*)d_in[2];
    const float* simWx  = (const float*)d_in[3];
    const float* simWq  = (const float*)d_in[4];
    const float* adjW   = (const float*)d_in[5];
    const float* gatW   = (const float*)d_in[6];
    const float* gatA1  = (const float*)d_in[7];
    const float* gatA2  = (const float*)d_in[8];
    const float* gatWo  = (const float*)d_in[9];
    const float* gatAo1 = (const float*)d_in[10];
    const float* gatAo2 = (const float*)d_in[11];
    const float* ln3g   = (const float*)d_in[12];
    const float* ln3b   = (const float*)d_in[13];
    const float* ln4g   = (const float*)d_in[14];
    const float* ln4b   = (const float*)d_in[15];
    const float* caWq   = (const float*)d_in[16];
    const float* caWk   = (const float*)d_in[17];
    const float* caWv   = (const float*)d_in[18];
    const float* caWv_  = caWv;
    const float* caWp   = (const float*)d_in[19];
    const float* gamma  = (const float*)d_in[20];
    (void)caWv_; (void)in_sizes; (void)n_in; (void)out_size;

    float* out = (float*)d_out;
    float* possim_out = out + (size_t)Bz * Nn * Dd;

    float *posq, *w, *sel, *fa, *connect, *Wh, *s1, *s2, *attn, *cat, *Who;
    float *so1, *so2, *attno, *gout, *qx, *kv, *q, *k, *v, *o;
    GETSYM(posq, g_posq);   GETSYM(w, g_w);       GETSYM(sel, g_sel);
    GETSYM(fa, g_fa);       GETSYM(connect, g_connect);
    GETSYM(Wh, g_Wh);       GETSYM(s1, g_s1);     GETSYM(s2, g_s2);
    GETSYM(attn, g_attn);   GETSYM(cat, g_cat);   GETSYM(Who, g_Who);
    GETSYM(so1, g_so1);     GETSYM(so2, g_so2);   GETSYM(attno, g_attno);
    GETSYM(gout, g_gout);   GETSYM(qx, g_qx);     GETSYM(kv, g_kv);
    GETSYM(q, g_q);         GETSYM(k, g_k);       GETSYM(v, g_v);
    GETSYM(o, g_o);

    const long zero = 0;

    // 1-3: selection path
    k_posquery<<<Bz, 256>>>(x, mask, posq);
    k_simvec<<<Bz, 256>>>(simWx, simWq, posq, w);
    k_possim<<<Bz * Nn / 8, 256>>>(x, w, possim_out, sel);

    // 4: fa = x @ adj_W  (flat M = B*N)
    gemm_k<false><<<dim3(Dd / BN, (Bz * Nn) / BM, 1), 256>>>(
        x, adjW, fa, Bz * Nn, Dd, Dd, Dd, Dd, Dd,
        1, zero, zero, zero, zero, zero, zero, EPI_NONE, nullptr, zero, nullptr);

    // 5: connect = (fa fa^T > 0) & sel_i & sel_j   (per batch)
    gemm_k<true><<<dim3(Nn / BN, Nn / BM, Bz), 256>>>(
        fa, fa, connect, Nn, Nn, Dd, Dd, Dd, Nn,
        1, (long)ND, zero, (long)ND, zero, (long)NNt, zero,
        EPI_CONNECT, sel, (long)Nn, nullptr);

    // 6: Wh[b,h] = x[b] @ gat_W[h]
    gemm_k<false><<<dim3(Dd / BN, Nn / BM, Bz * Hh), 256>>>(
        x, gatW, Wh, Nn, Dd, Dd, Dd, Dd, Dd,
        Hh, (long)ND, zero, zero, (long)Dd * Dd, (long)Hh * ND, (long)ND,
        EPI_NONE, nullptr, zero, nullptr);

    // 7: s1/s2 = Wh . a1/a2
    k_dot2<<<Bz * Hh * Nn / 8, 256>>>(Wh, gatA1, gatA2, s1, s2, Hh);

    // 8: GAT softmax
    k_softmax_gat<<<dim3(Nn, Bz * Hh), 256>>>(s1, s2, connect, attn, Hh);

    // 9: cat[b,:,h*D:(h+1)*D] = elu( attn[b,h] @ Wh[b,h] )
    gemm_k<false><<<dim3(Dd / BN, Nn / BM, Bz * Hh), 256>>>(
        attn, Wh, cat, Nn, Dd, Nn, Nn, Dd, HD,
        Hh, (long)Hh * NNt, (long)NNt, (long)Hh * ND, (long)ND,
        (long)Nn * HD, (long)Dd,
        EPI_ELU, nullptr, zero, nullptr);

    // 10: Who = cat @ gat_Wo
    gemm_k<false><<<dim3(Dd / BN, Nn / BM, Bz), 256>>>(
        cat, gatWo, Who, Nn, Dd, HD, HD, Dd, Dd,
        1, (long)Nn * HD, zero, zero, zero, (long)ND, zero,
        EPI_NONE, nullptr, zero, nullptr);

    // 11: so1/so2 = Who . ao1/ao2
    k_dot2<<<Bz * Nn / 8, 256>>>(Who, gatAo1, gatAo2, so1, so2, 1);

    // 12: out-layer softmax
    k_softmax_gat<<<dim3(Nn, Bz), 256>>>(so1, so2, connect, attno, 1);

    // 13: gout = elu( attn_o @ Who )
    gemm_k<false><<<dim3(Dd / BN, Nn / BM, Bz), 256>>>(
        attno, Who, gout, Nn, Dd, Nn, Nn, Dd, Dd,
        1, (long)NNt, zero, (long)ND, zero, (long)ND, zero,
        EPI_ELU, nullptr, zero, nullptr);

    // 14-15: LayerNorms
    k_ln<<<Bz * Nn / 8, 256>>>(x, ln3g, ln3b, qx);
    k_qfull_ln<<<Bz * Nn / 8, 256>>>(gout, pe, sel, ln4g, ln4b, kv);

    // 16: q/k/v projections (flat M = B*N)
    gemm_k<false><<<dim3(Dd / BN, (Bz * Nn) / BM, 1), 256>>>(
        qx, caWq, q, Bz * Nn, Dd, Dd, Dd, Dd, Dd,
        1, zero, zero, zero, zero, zero, zero, EPI_NONE, nullptr, zero, nullptr);
    gemm_k<false><<<dim3(Dd / BN, (Bz * Nn) / BM, 1), 256>>>(
        kv, caWk, k, Bz * Nn, Dd, Dd, Dd, Dd, Dd,
        1, zero, zero, zero, zero, zero, zero, EPI_NONE, nullptr, zero, nullptr);
    gemm_k<false><<<dim3(Dd / BN, (Bz * Nn) / BM, 1), 256>>>(
        kv, caWv, v, Bz * Nn, Dd, Dd, Dd, Dd, Dd,
        1, zero, zero, zero, zero, zero, zero, EPI_NONE, nullptr, zero, nullptr);

    // 17: CA logits (reuse attn buffer): z = b*HC+hc
    gemm_k<true><<<dim3(Nn / BN, Nn / BM, Bz * HC), 256>>>(
        q, k, attn, Nn, Nn, DH, Dd, Dd, Nn,
        HC, (long)ND, (long)DH, (long)ND, (long)DH, (long)HC * NNt, (long)NNt,
        EPI_NONE, nullptr, zero, nullptr);

    // 18: CA softmax (in place, applies 1/8 scale + key mask)
    k_softmax_ca<<<dim3(Nn, Bz * HC), 256>>>(attn, sel);

    // 19: o[b,:,hc*64:] = a[b,hc] @ v[b,:,hc*64:]
    gemm_k<false><<<dim3(DH / BN, Nn / BM, Bz * HC), 256>>>(
        attn, v, o, Nn, DH, Nn, Nn, Dd, Dd,
        HC, (long)HC * NNt, (long)NNt, (long)ND, (long)DH, (long)ND, (long)DH,
        EPI_NONE, nullptr, zero, nullptr);

    // 20: out = x + gamma * (o @ ca_Wp)
    gemm_k<false><<<dim3(Dd / BN, (Bz * Nn) / BM, 1), 256>>>(
        o, caWp, out, Bz * Nn, Dd, Dd, Dd, Dd, Dd,
        1, zero, zero, zero, zero, zero, zero,
        EPI_RESID, x, zero, gamma);
}

// round 3
// speedup vs baseline: 2.0144x; 2.0144x over previous
#include <cuda_runtime.h>
#include <cuda_bf16.h>
#include <math.h>
#include <stdint.h>

// Problem constants
#define Bz 8
#define Nn 1024
#define Dd 256
#define Hh 8
#define HC 4
#define DH 64
#define HD 2048                 // Hh*Dd
#define ND (Nn*Dd)              // 262144
#define NNt ((size_t)Nn*Nn)     // 1048576

// ---------------- scratch (device globals) ----------------
__device__ float g_posq[Bz*Dd];
__device__ float g_w[Bz*Dd];
__device__ float g_sel[Bz*Nn];
__device__ float g_fa[Bz*ND];
__device__ float g_connect[(size_t)Bz*Nn*Nn];
__device__ float g_Wh[(size_t)Bz*Hh*ND];
__device__ float g_WhT[(size_t)Bz*Hh*ND];
__device__ float g_s1[Bz*Hh*Nn];
__device__ float g_s2[Bz*Hh*Nn];
__device__ float g_attn[(size_t)Bz*Hh*Nn*Nn];
__device__ float g_cat[(size_t)Bz*Nn*HD];
__device__ float g_Who[Bz*ND];
__device__ float g_WhoT[Bz*ND];
__device__ float g_so1[Bz*Nn];
__device__ float g_so2[Bz*Nn];
__device__ float g_attno[(size_t)Bz*Nn*Nn];
__device__ float g_gout[Bz*ND];
__device__ float g_qx[Bz*ND];
__device__ float g_kv[Bz*ND];
__device__ float g_q[Bz*ND];
__device__ float g_k[Bz*ND];
__device__ float g_v[Bz*ND];
__device__ float g_vT[Bz*ND];
__device__ float g_o[Bz*ND];
// transposed weights
__device__ float g_adjWT[Dd*Dd];
__device__ float g_gatWT[Hh*Dd*Dd];
__device__ float g_WoT[HD*Dd];
__device__ float g_caWqT[Dd*Dd];
__device__ float g_caWkT[Dd*Dd];
__device__ float g_caWvT[Dd*Dd];
__device__ float g_caWpT[Dd*Dd];

// ---------------- low-level helpers ----------------
__device__ __forceinline__ uint32_t smem_u32(const void* p) {
    uint32_t a;
    asm("{ .reg .u64 t; cvta.to.shared.u64 t, %1; cvt.u32.u64 %0, t; }" : "=r"(a) : "l"(p));
    return a;
}
__device__ __forceinline__ void ldsm4(uint32_t* r, uint32_t addr) {
    asm volatile("ldmatrix.sync.aligned.m8n8.x4.shared.b16 {%0,%1,%2,%3}, [%4];"
        : "=r"(r[0]), "=r"(r[1]), "=r"(r[2]), "=r"(r[3]) : "r"(addr));
}
__device__ __forceinline__ void mma16816(float* c, const uint32_t* a, const uint32_t* b) {
    asm volatile("mma.sync.aligned.m16n8k16.row.col.f32.bf16.bf16.f32 "
        "{%0,%1,%2,%3}, {%4,%5,%6,%7}, {%8,%9}, {%0,%1,%2,%3};"
        : "+f"(c[0]), "+f"(c[1]), "+f"(c[2]), "+f"(c[3])
        : "r"(a[0]), "r"(a[1]), "r"(a[2]), "r"(a[3]), "r"(b[0]), "r"(b[1]));
}
// pack (v0 -> low half, v1 -> high half)
__device__ __forceinline__ uint32_t packbf(float v0, float v1) {
    uint32_t r;
    asm("cvt.rn.bf16x2.f32 %0, %1, %2;" : "=r"(r) : "f"(v1), "f"(v0));
    return r;
}
// split float4 into bf16-hi pack and bf16-lo pack (2-term split)
__device__ __forceinline__ void split4(float4 v, uint2& h, uint2& l) {
    float h0 = __bfloat162float(__float2bfloat16(v.x));
    float h1 = __bfloat162float(__float2bfloat16(v.y));
    float h2 = __bfloat162float(__float2bfloat16(v.z));
    float h3 = __bfloat162float(__float2bfloat16(v.w));
    h.x = packbf(h0, h1); h.y = packbf(h2, h3);
    l.x = packbf(v.x - h0, v.y - h1);
    l.y = packbf(v.z - h2, v.w - h3);
}

// ---------------- transpose kernel ----------------
__global__ void k_transpose(const float* __restrict__ src, float* __restrict__ dst,
                            int R, int C, long sz_src, long sz_dst)
{
    __shared__ float t[32][33];
    const float* s = src + (size_t)blockIdx.z * sz_src;
    float* d = dst + (size_t)blockIdx.z * sz_dst;
    int bx = blockIdx.x * 32, by = blockIdx.y * 32;
    int tx = threadIdx.x, ty = threadIdx.y;
    #pragma unroll
    for (int i = 0; i < 32; i += 8)
        t[ty + i][tx] = s[(size_t)(by + ty + i) * C + bx + tx];
    __syncthreads();
    #pragma unroll
    for (int i = 0; i < 32; i += 8)
        d[(size_t)(bx + ty + i) * R + by + tx] = t[tx][ty + i];
}

// ---------------- bf16x3 mma.sync NT GEMM ----------------
// C[M,N] = A[M,K] @ B[N,K]^T, fp32 in/out, bf16 2-term split, 3 products, fp32 acc.
// Block: 256 threads = 8 warps, warp tile 64x32 (4x4 m16n8k16 mmas).
// BM x BN block tile; WM x WN warp grid with WM*64==BM, WN*32==BN. KTILE=32.
enum { EPI_NONE = 0, EPI_ELU = 1, EPI_CONNECT = 2, EPI_RESID = 3 };
#define ROWB 80   // padded SMEM row stride in bytes (32 bf16 = 64B + 16B pad)

template <int BM, int BN, int WM, int WN, int EPI, bool DUAL>
__global__ void __launch_bounds__(256, 1)
mma_gemm(const float* __restrict__ A, const float* __restrict__ Bm, float* __restrict__ C,
         int K, int lda, int ldb, int ldc, int zInner,
         long sAb, long sAi, long sBb, long sBi, long sCb, long sCi,
         const float* __restrict__ e1, long sE1b, const float* __restrict__ e2,
         float* __restrict__ Ct, long sCtb, long sCti, int ldct)
{
    constexpr int ABYTES = BM * ROWB;   // one plane
    constexpr int BBYTES = BN * ROWB;
    constexpr int APASS = BM / 32;
    constexpr int BPASS = BN / 32;

    extern __shared__ char smem[];
    const uint32_t sb = smem_u32(smem);

    const int tid = threadIdx.x;
    const int wid = tid >> 5;
    const int lane = tid & 31;

    const int z = blockIdx.z;
    const int zb = z / zInner, zi = z % zInner;
    const float* Ap = A + (size_t)zb * sAb + (size_t)zi * sAi;
    const float* Bp = Bm + (size_t)zb * sBb + (size_t)zi * sBi;
    float* Cp = C + (size_t)zb * sCb + (size_t)zi * sCi;
    const float* e1p = e1 ? (e1 + (size_t)zb * sE1b) : nullptr;

    const int m0 = blockIdx.y * BM;
    const int n0 = blockIdx.x * BN;

    // loader indices
    const int lq = tid & 7;          // k-quad (4 floats)
    const int lr = tid >> 3;         // base row (32 rows per pass)

    // compute indices
    const int wid_m = wid % WM;
    const int wid_n = wid / WM;
    const int g = lane >> 3, rl = lane & 7;
    const int aRowBase = wid_m * 64 + (g & 1) * 8 + rl;
    const int aKsel = (g >> 1) * 8;
    const int bRowBase = wid_n * 32 + (g >> 1) * 8 + rl;
    const int bKsel = (g & 1) * 8;

    float acc[4][4][4] = {};
    float4 pa[APASS], pb[BPASS];

    const int nkt = K >> 5;

    // prologue: load tile 0, store stage 0
    #pragma unroll
    for (int i = 0; i < APASS; i++)
        pa[i] = *reinterpret_cast<const float4*>(Ap + (size_t)(m0 + lr + 32 * i) * lda + lq * 4);
    #pragma unroll
    for (int i = 0; i < BPASS; i++)
        pb[i] = *reinterpret_cast<const float4*>(Bp + (size_t)(n0 + lr + 32 * i) * ldb + lq * 4);
    #pragma unroll
    for (int i = 0; i < APASS; i++) {
        uint2 h, l; split4(pa[i], h, l);
        int off = (lr + 32 * i) * ROWB + lq * 8;
        *reinterpret_cast<uint2*>(smem + off) = h;
        *reinterpret_cast<uint2*>(smem + ABYTES + off) = l;
    }
    #pragma unroll
    for (int i = 0; i < BPASS; i++) {
        uint2 h, l; split4(pb[i], h, l);
        int off = 4 * ABYTES + (lr + 32 * i) * ROWB + lq * 8;
        *reinterpret_cast<uint2*>(smem + off) = h;
        *reinterpret_cast<uint2*>(smem + BBYTES + off) = l;
    }
    __syncthreads();

    for (int kt = 0; kt < nkt; kt++) {
        const int stage = kt & 1;
        const bool more = (kt + 1 < nkt);
        if (more) {
            const int kk = (kt + 1) << 5;
            #pragma unroll
            for (int i = 0; i < APASS; i++)
                pa[i] = *reinterpret_cast<const float4*>(Ap + (size_t)(m0 + lr + 32 * i) * lda + kk + lq * 4);
            #pragma unroll
            for (int i = 0; i < BPASS; i++)
                pb[i] = *reinterpret_cast<const float4*>(Bp + (size_t)(n0 + lr + 32 * i) * ldb + kk + lq * 4);
        }

        const uint32_t sAhi = sb + (stage * 2) * ABYTES;
        const uint32_t sAlo = sAhi + ABYTES;
        const uint32_t sBhi = sb + 4 * ABYTES + (stage * 2) * BBYTES;
        const uint32_t sBlo = sBhi + BBYTES;

        #pragma unroll
        for (int j = 0; j < 2; j++) {
            const int kb = j * 16;
            uint32_t a[4][4], bh[4][2], bl[4][2];
            #pragma unroll
            for (int im = 0; im < 4; im++)
                ldsm4(a[im], sAhi + (uint32_t)((aRowBase + im * 16) * ROWB + (kb + aKsel) * 2));
            #pragma unroll
            for (int i2 = 0; i2 < 2; i2++) {
                uint32_t t[4];
                ldsm4(t, sBhi + (uint32_t)((bRowBase + i2 * 16) * ROWB + (kb + bKsel) * 2));
                bh[2 * i2][0] = t[0]; bh[2 * i2][1] = t[1];
                bh[2 * i2 + 1][0] = t[2]; bh[2 * i2 + 1][1] = t[3];
            }
            #pragma unroll
            for (int im = 0; im < 4; im++)
                #pragma unroll
                for (int in = 0; in < 4; in++)
                    mma16816(acc[im][in], a[im], bh[in]);       // Ah*Bh
            #pragma unroll
            for (int i2 = 0; i2 < 2; i2++) {
                uint32_t t[4];
                ldsm4(t, sBlo + (uint32_t)((bRowBase + i2 * 16) * ROWB + (kb + bKsel) * 2));
                bl[2 * i2][0] = t[0]; bl[2 * i2][1] = t[1];
                bl[2 * i2 + 1][0] = t[2]; bl[2 * i2 + 1][1] = t[3];
            }
            #pragma unroll
            for (int im = 0; im < 4; im++)
                #pragma unroll
                for (int in = 0; in < 4; in++)
                    mma16816(acc[im][in], a[im], bl[in]);       // Ah*Bl
            #pragma unroll
            for (int im = 0; im < 4; im++)
                ldsm4(a[im], sAlo + (uint32_t)((aRowBase + im * 16) * ROWB + (kb + aKsel) * 2));
            #pragma unroll
            for (int im = 0; im < 4; im++)
                #pragma unroll
                for (int in = 0; in < 4; in++)
                    mma16816(acc[im][in], a[im], bh[in]);       // Al*Bh
        }

        if (more) {
            const int st2 = (stage ^ 1) * 2;
            #pragma unroll
            for (int i = 0; i < APASS; i++) {
                uint2 h, l; split4(pa[i], h, l);
                int off = st2 * ABYTES + (lr + 32 * i) * ROWB + lq * 8;
                *reinterpret_cast<uint2*>(smem + off) = h;
                *reinterpret_cast<uint2*>(smem + ABYTES + off) = l;
            }
            #pragma unroll
            for (int i = 0; i < BPASS; i++) {
                uint2 h, l; split4(pb[i], h, l);
                int off = 4 * ABYTES + st2 * BBYTES + (lr + 32 * i) * ROWB + lq * 8;
                *reinterpret_cast<uint2*>(smem + off) = h;
                *reinterpret_cast<uint2*>(smem + BBYTES + off) = l;
            }
        }
        __syncthreads();
    }

    // epilogue
    const int mw = m0 + wid_m * 64;
    const int nw = n0 + wid_n * 32;
    float* Ctp = DUAL ? (Ct + (size_t)zb * sCtb + (size_t)zi * sCti) : nullptr;
    #pragma unroll
    for (int im = 0; im < 4; im++) {
        const int row = mw + im * 16 + (lane >> 2);
        const float sr0 = (EPI == EPI_CONNECT) ? e1p[row] : 0.f;
        const float sr1 = (EPI == EPI_CONNECT) ? e1p[row + 8] : 0.f;
        #pragma unroll
        for (int in = 0; in < 4; in++) {
            const int col = nw + in * 8 + (lane & 3) * 2;
            float v00 = acc[im][in][0], v01 = acc[im][in][1];
            float v10 = acc[im][in][2], v11 = acc[im][in][3];
            if (EPI == EPI_ELU) {
                v00 = v00 > 0.f ? v00 : expm1f(v00);
                v01 = v01 > 0.f ? v01 : expm1f(v01);
                v10 = v10 > 0.f ? v10 : expm1f(v10);
                v11 = v11 > 0.f ? v11 : expm1f(v11);
            } else if (EPI == EPI_CONNECT) {
                const float sc0 = e1p[col], sc1 = e1p[col + 1];
                v00 = (v00 > 0.f && sr0 > 0.5f && sc0 > 0.5f) ? 1.f : 0.f;
                v01 = (v01 > 0.f && sr0 > 0.5f && sc1 > 0.5f) ? 1.f : 0.f;
                v10 = (v10 > 0.f && sr1 > 0.5f && sc0 > 0.5f) ? 1.f : 0.f;
                v11 = (v11 > 0.f && sr1 > 0.5f && sc1 > 0.5f) ? 1.f : 0.f;
            } else if (EPI == EPI_RESID) {
                const float g0 = e2[col], g1 = e2[col + 1];
                const size_t r0 = (size_t)row * ldc + col;
                const size_t r1 = (size_t)(row + 8) * ldc + col;
                v00 = e1p[r0] + g0 * v00; v01 = e1p[r0 + 1] + g1 * v01;
                v10 = e1p[r1] + g0 * v10; v11 = e1p[r1 + 1] + g1 * v11;
            }
            *reinterpret_cast<float2*>(Cp + (size_t)row * ldc + col) = make_float2(v00, v01);
            *reinterpret_cast<float2*>(Cp + (size_t)(row + 8) * ldc + col) = make_float2(v10, v11);
            if (DUAL) {
                Ctp[(size_t)col * ldct + row] = v00;
                Ctp[(size_t)(col + 1) * ldct + row] = v01;
                Ctp[(size_t)col * ldct + row + 8] = v10;
                Ctp[(size_t)(col + 1) * ldct + row + 8] = v11;
            }
        }
    }
}

// ---------------- auxiliary kernels ----------------
__global__ void k_posquery(const float* __restrict__ x, const int* __restrict__ mask,
                           float* __restrict__ pq)
{
    int b = blockIdx.x, d = threadIdx.x;
    float s = 0.f, cnt = 0.f;
    for (int n = 0; n < Nn; n++) {
        int m = mask[b * Nn + n];
        if (m == 1) { s += x[((size_t)b * Nn + n) * Dd + d]; cnt += 1.f; }
    }
    pq[b * Dd + d] = s / fmaxf(cnt, 1.f);
}

__global__ void k_simvec(const float* __restrict__ Wx, const float* __restrict__ Wq,
                         const float* __restrict__ pq, float* __restrict__ w)
{
    __shared__ float spq[Dd];
    __shared__ float qs[Dd];
    int b = blockIdx.x, t = threadIdx.x;
    spq[t] = pq[b * Dd + t];
    __syncthreads();
    float a = 0.f;
    for (int i = 0; i < Dd; i++) a += spq[i] * Wq[i * Dd + t];
    qs[t] = a;
    __syncthreads();
    float a2 = 0.f;
    for (int j = 0; j < Dd; j++) a2 += Wx[t * Dd + j] * qs[j];
    w[b * Dd + t] = a2;
}

__global__ void k_possim(const float* __restrict__ x, const float* __restrict__ w,
                         float* __restrict__ possim_out, float* __restrict__ sel)
{
    int row = blockIdx.x * 8 + (threadIdx.x >> 5);
    int lane = threadIdx.x & 31;
    int b = row / Nn;
    float s = 0.f;
    for (int e = lane; e < Dd; e += 32) s += x[(size_t)row * Dd + e] * w[b * Dd + e];
    #pragma unroll
    for (int o = 16; o; o >>= 1) s += __shfl_xor_sync(0xffffffffu, s, o);
    if (lane == 0) {
        float p = 1.f / (1.f + expf(-s * 0.0625f));
        possim_out[row] = p;
        sel[row] = (p > 0.97f) ? 1.f : 0.f;
    }
}

__global__ void k_dot2(const float* __restrict__ rows, const float* __restrict__ a1,
                       const float* __restrict__ a2, float* __restrict__ s1,
                       float* __restrict__ s2, int nheads)
{
    int row = blockIdx.x * 8 + (threadIdx.x >> 5);
    int lane = threadIdx.x & 31;
    int head = (row / Nn) % nheads;
    const float* rp = rows + (size_t)row * Dd;
    const float* a1p = a1 + head * Dd;
    const float* a2p = a2 + head * Dd;
    float u = 0.f, v = 0.f;
    for (int e = lane; e < Dd; e += 32) {
        float rv = rp[e];
        u += rv * a1p[e];
        v += rv * a2p[e];
    }
    #pragma unroll
    for (int o = 16; o; o >>= 1) {
        u += __shfl_xor_sync(0xffffffffu, u, o);
        v += __shfl_xor_sync(0xffffffffu, v, o);
    }
    if (lane == 0) { s1[row] = u; s2[row] = v; }
}

__global__ void k_softmax_gat(const float* __restrict__ s1, const float* __restrict__ s2,
                              const float* __restrict__ connect, float* __restrict__ attn,
                              int nheads)
{
    __shared__ float red[256];
    int i = blockIdx.x;
    int z = blockIdx.y;
    int b = z / nheads;
    const float* con = connect + (size_t)b * NNt + (size_t)i * Nn;
    const float* s2p = s2 + (size_t)z * Nn;
    float s1v = s1[(size_t)z * Nn + i];
    int t = threadIdx.x;
    float v[4];
    float mx = -INFINITY;
    #pragma unroll
    for (int k = 0; k < 4; k++) {
        int j = t + k * 256;
        float e = s1v + s2p[j];
        e = (e >= 0.f) ? e : 0.2f * e;
        v[k] = (con[j] > 0.5f) ? e : -9.0e15f;
        mx = fmaxf(mx, v[k]);
    }
    red[t] = mx; __syncthreads();
    for (int s = 128; s > 0; s >>= 1) { if (t < s) red[t] = fmaxf(red[t], red[t + s]); __syncthreads(); }
    mx = red[0]; __syncthreads();
    float sum = 0.f;
    #pragma unroll
    for (int k = 0; k < 4; k++) { v[k] = expf(v[k] - mx); sum += v[k]; }
    red[t] = sum; __syncthreads();
    for (int s = 128; s > 0; s >>= 1) { if (t < s) red[t] += red[t + s]; __syncthreads(); }
    float inv = 1.f / red[0];
    float* out = attn + (size_t)z * NNt + (size_t)i * Nn;
    #pragma unroll
    for (int k = 0; k < 4; k++) out[t + k * 256] = v[k] * inv;
}

__global__ void k_softmax_ca(float* __restrict__ logits, const float* __restrict__ sel)
{
    __shared__ float red[256];
    int i = blockIdx.x;
    int z = blockIdx.y;
    int b = z / HC;
    float* row = logits + (size_t)z * NNt + (size_t)i * Nn;
    const float* sp = sel + b * Nn;
    int t = threadIdx.x;
    float v[4];
    float mx = -INFINITY;
    #pragma unroll
    for (int k = 0; k < 4; k++) {
        int j = t + k * 256;
        v[k] = (sp[j] > 0.5f) ? row[j] * 0.125f : -1.0e9f;
        mx = fmaxf(mx, v[k]);
    }
    red[t] = mx; __syncthreads();
    for (int s = 128; s > 0; s >>= 1) { if (t < s) red[t] = fmaxf(red[t], red[t + s]); __syncthreads(); }
    mx = red[0]; __syncthreads();
    float sum = 0.f;
    #pragma unroll
    for (int k = 0; k < 4; k++) { v[k] = expf(v[k] - mx); sum += v[k]; }
    red[t] = sum; __syncthreads();
    for (int s = 128; s > 0; s >>= 1) { if (t < s) red[t] += red[t + s]; __syncthreads(); }
    float inv = 1.f / red[0];
    #pragma unroll
    for (int k = 0; k < 4; k++) row[t + k * 256] = v[k] * inv;
}

__global__ void k_ln(const float* __restrict__ in, const float* __restrict__ g,
                     const float* __restrict__ bb, float* __restrict__ out)
{
    int row = blockIdx.x * 8 + (threadIdx.x >> 5);
    int lane = threadIdx.x & 31;
    size_t base = (size_t)row * Dd;
    float vbuf[8];
    float s = 0.f, sq = 0.f;
    #pragma unroll
    for (int k = 0; k < 8; k++) {
        float x = in[base + lane + k * 32];
        vbuf[k] = x; s += x; sq += x * x;
    }
    #pragma unroll
    for (int o = 16; o; o >>= 1) {
        s += __shfl_xor_sync(0xffffffffu, s, o);
        sq += __shfl_xor_sync(0xffffffffu, sq, o);
    }
    float mean = s * (1.f / Dd);
    float var = sq * (1.f / Dd) - mean * mean;
    float rstd = rsqrtf(var + 1e-5f);
    #pragma unroll
    for (int k = 0; k < 8; k++) {
        int d = lane + k * 32;
        out[base + d] = (vbuf[k] - mean) * rstd * g[d] + bb[d];
    }
}

__global__ void k_qfull_ln(const float* __restrict__ gout, const float* __restrict__ pe,
                           const float* __restrict__ sel, const float* __restrict__ g,
                           const float* __restrict__ bb, float* __restrict__ out)
{
    int row = blockIdx.x * 8 + (threadIdx.x >> 5);
    int lane = threadIdx.x & 31;
    int n = row % Nn;
    size_t base = (size_t)row * Dd;
    float selv = sel[row];
    float vbuf[8];
    float s = 0.f, sq = 0.f;
    #pragma unroll
    for (int k = 0; k < 8; k++) {
        int d = lane + k * 32;
        float x = (selv > 0.5f) ? (gout[base + d] + pe[(size_t)n * Dd + d]) : 0.f;
        vbuf[k] = x; s += x; sq += x * x;
    }
    #pragma unroll
    for (int o = 16; o; o >>= 1) {
        s += __shfl_xor_sync(0xffffffffu, s, o);
        sq += __shfl_xor_sync(0xffffffffu, sq, o);
    }
    float mean = s * (1.f / Dd);
    float var = sq * (1.f / Dd) - mean * mean;
    float rstd = rsqrtf(var + 1e-5f);
    #pragma unroll
    for (int k = 0; k < 8; k++) {
        int d = lane + k * 32;
        out[base + d] = (vbuf[k] - mean) * rstd * g[d] + bb[d];
    }
}

// ---------------- launch ----------------
#define GETSYM(p, s) do { void* _t; cudaGetSymbolAddress(&_t, s); p = (float*)_t; } while (0)
#define SMEMSZ(BM, BN) (4 * (BM) * ROWB + 4 * (BN) * ROWB)

extern "C" void kernel_launch(void* const* d_in, const int* in_sizes, int n_in,
                              void* d_out, int out_size)
{
    const float* x      = (const float*)d_in[0];
    const int*   mask   = (const int*)  d_in[1];
    const float* pe     = (const float*)d_in[2];
    const float* simWx  = (const float*)d_in[3];
    const float* simWq  = (const float*)d_in[4];
    const float* adjW   = (const float*)d_in[5];
    const float* gatW   = (const float*)d_in[6];
    const float* gatA1  = (const float*)d_in[7];
    const float* gatA2  = (const float*)d_in[8];
    const float* gatWo  = (const float*)d_in[9];
    const float* gatAo1 = (const float*)d_in[10];
    const float* gatAo2 = (const float*)d_in[11];
    const float* ln3g   = (const float*)d_in[12];
    const float* ln3b   = (const float*)d_in[13];
    const float* ln4g   = (const float*)d_in[14];
    const float* ln4b   = (const float*)d_in[15];
    const float* caWq   = (const float*)d_in[16];
    const float* caWk   = (const float*)d_in[17];
    const float* caWv   = (const float*)d_in[18];
    const float* caWp   = (const float*)d_in[19];
    const float* gamma  = (const float*)d_in[20];
    (void)in_sizes; (void)n_in; (void)out_size;

    float* out = (float*)d_out;
    float* possim_out = out + (size_t)Bz * Nn * Dd;

    float *posq, *w, *sel, *fa, *connect, *Wh, *WhT, *s1, *s2, *attn, *cat, *Who, *WhoT;
    float *so1, *so2, *attno, *gout, *qx, *kv, *q, *k, *v, *vT, *o;
    float *adjWT, *gatWT, *WoT, *caWqT, *caWkT, *caWvT, *caWpT;
    GETSYM(posq, g_posq);   GETSYM(w, g_w);       GETSYM(sel, g_sel);
    GETSYM(fa, g_fa);       GETSYM(connect, g_connect);
    GETSYM(Wh, g_Wh);       GETSYM(WhT, g_WhT);
    GETSYM(s1, g_s1);       GETSYM(s2, g_s2);
    GETSYM(attn, g_attn);   GETSYM(cat, g_cat);
    GETSYM(Who, g_Who);     GETSYM(WhoT, g_WhoT);
    GETSYM(so1, g_so1);     GETSYM(so2, g_so2);   GETSYM(attno, g_attno);
    GETSYM(gout, g_gout);   GETSYM(qx, g_qx);     GETSYM(kv, g_kv);
    GETSYM(q, g_q);         GETSYM(k, g_k);       GETSYM(v, g_v);
    GETSYM(vT, g_vT);       GETSYM(o, g_o);
    GETSYM(adjWT, g_adjWT); GETSYM(gatWT, g_gatWT); GETSYM(WoT, g_WoT);
    GETSYM(caWqT, g_caWqT); GETSYM(caWkT, g_caWkT); GETSYM(caWvT, g_caWvT); GETSYM(caWpT, g_caWpT);

    // config A: 128x128 block (warps 2x4); config B: 256x64 block (warps 4x2)
    const int SMA = SMEMSZ(128, 128);
    const int SMB = SMEMSZ(256, 64);
    cudaFuncSetAttribute(mma_gemm<128,128,2,4,EPI_NONE,false>,    cudaFuncAttributeMaxDynamicSharedMemorySize, SMA);
    cudaFuncSetAttribute(mma_gemm<128,128,2,4,EPI_NONE,true>,     cudaFuncAttributeMaxDynamicSharedMemorySize, SMA);
    cudaFuncSetAttribute(mma_gemm<128,128,2,4,EPI_ELU,false>,     cudaFuncAttributeMaxDynamicSharedMemorySize, SMA);
    cudaFuncSetAttribute(mma_gemm<128,128,2,4,EPI_CONNECT,false>, cudaFuncAttributeMaxDynamicSharedMemorySize, SMA);
    cudaFuncSetAttribute(mma_gemm<128,128,2,4,EPI_RESID,false>,   cudaFuncAttributeMaxDynamicSharedMemorySize, SMA);
    cudaFuncSetAttribute(mma_gemm<256,64,4,2,EPI_NONE,false>,     cudaFuncAttributeMaxDynamicSharedMemorySize, SMB);

    const long zero = 0;
    dim3 tb(32, 8);

    // 0: weight transposes (B operands become [N,K] K-major)
    k_transpose<<<dim3(8, 8, 1), tb>>>(adjW,  adjWT, Dd, Dd, 0, 0);
    k_transpose<<<dim3(8, 8, Hh), tb>>>(gatW, gatWT, Dd, Dd, (long)Dd * Dd, (long)Dd * Dd);
    k_transpose<<<dim3(8, 64, 1), tb>>>(gatWo, WoT, HD, Dd, 0, 0);
    k_transpose<<<dim3(8, 8, 1), tb>>>(caWq, caWqT, Dd, Dd, 0, 0);
    k_transpose<<<dim3(8, 8, 1), tb>>>(caWk, caWkT, Dd, Dd, 0, 0);
    k_transpose<<<dim3(8, 8, 1), tb>>>(caWv, caWvT, Dd, Dd, 0, 0);
    k_transpose<<<dim3(8, 8, 1), tb>>>(caWp, caWpT, Dd, Dd, 0, 0);

    // 1-3: selection path
    k_posquery<<<Bz, 256>>>(x, mask, posq);
    k_simvec<<<Bz, 256>>>(simWx, simWq, posq, w);
    k_possim<<<Bz * Nn / 8, 256>>>(x, w, possim_out, sel);

    // 4: fa = x @ adjW
    mma_gemm<128,128,2,4,EPI_NONE,false><<<dim3(2, 64, 1), 256, SMA>>>(
        x, adjWT, fa, Dd, Dd, Dd, Dd,
        1, zero, zero, zero, zero, zero, zero,
        nullptr, zero, nullptr, nullptr, zero, zero, 0);

    // 5: connect = (fa fa^T > 0) & sel_i & sel_j (per batch)
    mma_gemm<128,128,2,4,EPI_CONNECT,false><<<dim3(8, 8, Bz), 256, SMA>>>(
        fa, fa, connect, Dd, Dd, Dd, Nn,
        1, (long)ND, zero, (long)ND, zero, (long)NNt, zero,
        sel, (long)Nn, nullptr, nullptr, zero, zero, 0);

    // 6: Wh[b,h] = x[b] @ gatW[h]; dual-write WhT
    mma_gemm<128,128,2,4,EPI_NONE,true><<<dim3(2, 8, Bz * Hh), 256, SMA>>>(
        x, gatWT, Wh, Dd, Dd, Dd, Dd,
        Hh, (long)ND, zero, zero, (long)Dd * Dd, (long)Hh * ND, (long)ND,
        nullptr, zero, nullptr, WhT, (long)Hh * ND, (long)ND, Nn);

    // 7: s1/s2 = Wh . a1/a2
    k_dot2<<<Bz * Hh * Nn / 8, 256>>>(Wh, gatA1, gatA2, s1, s2, Hh);

    // 8: GAT softmax
    k_softmax_gat<<<dim3(Nn, Bz * Hh), 256>>>(s1, s2, connect, attn, Hh);

    // 9: cat[b,:,h*D:(h+1)*D] = elu( attn[b,h] @ Wh[b,h] )
    mma_gemm<128,128,2,4,EPI_ELU,false><<<dim3(2, 8, Bz * Hh), 256, SMA>>>(
        attn, WhT, cat, Nn, Nn, Nn, HD,
        Hh, (long)Hh * NNt, (long)NNt, (long)Hh * ND, (long)ND, (long)Nn * HD, (long)Dd,
        nullptr, zero, nullptr, nullptr, zero, zero, 0);

    // 10: Who = cat @ gatWo; dual-write WhoT
    mma_gemm<128,128,2,4,EPI_NONE,true><<<dim3(2, 8, Bz), 256, SMA>>>(
        cat, WoT, Who, HD, HD, HD, Dd,
        1, (long)Nn * HD, zero, zero, zero, (long)ND, zero,
        nullptr, zero, nullptr, WhoT, (long)ND, zero, Nn);

    // 11: so1/so2
    k_dot2<<<Bz * Nn / 8, 256>>>(Who, gatAo1, gatAo2, so1, so2, 1);

    // 12: out-layer softmax
    k_softmax_gat<<<dim3(Nn, Bz), 256>>>(so1, so2, connect, attno, 1);

    // 13: gout = elu( attn_o @ Who )
    mma_gemm<128,128,2,4,EPI_ELU,false><<<dim3(2, 8, Bz), 256, SMA>>>(
        attno, WhoT, gout, Nn, Nn, Nn, Dd,
        1, (long)NNt, zero, (long)ND, zero, (long)ND, zero,
        nullptr, zero, nullptr, nullptr, zero, zero, 0);

    // 14-15: LayerNorms
    k_ln<<<Bz * Nn / 8, 256>>>(x, ln3g, ln3b, qx);
    k_qfull_ln<<<Bz * Nn / 8, 256>>>(gout, pe, sel, ln4g, ln4b, kv);

    // 16: q/k projections (flat), v (batched, dual transposed write)
    mma_gemm<128,128,2,4,EPI_NONE,false><<<dim3(2, 64, 1), 256, SMA>>>(
        qx, caWqT, q, Dd, Dd, Dd, Dd,
        1, zero, zero, zero, zero, zero, zero,
        nullptr, zero, nullptr, nullptr, zero, zero, 0);
    mma_gemm<128,128,2,4,EPI_NONE,false><<<dim3(2, 64, 1), 256, SMA>>>(
        kv, caWkT, k, Dd, Dd, Dd, Dd,
        1, zero, zero, zero, zero, zero, zero,
        nullptr, zero, nullptr, nullptr, zero, zero, 0);
    mma_gemm<128,128,2,4,EPI_NONE,true><<<dim3(2, 8, Bz), 256, SMA>>>(
        kv, caWvT, v, Dd, Dd, Dd, Dd,
        1, (long)ND, zero, zero, zero, (long)ND, zero,
        nullptr, zero, nullptr, vT, (long)ND, zero, Nn);

    // 17: CA logits = q k^T per (b,hc), reuse attn buffer
    mma_gemm<128,128,2,4,EPI_NONE,false><<<dim3(8, 8, Bz * HC), 256, SMA>>>(
        q, k, attn, DH, Dd, Dd, Nn,
        HC, (long)ND, (long)DH, (long)ND, (long)DH, (long)HC * NNt, (long)NNt,
        nullptr, zero, nullptr, nullptr, zero, zero, 0);

    // 18: CA softmax (in place, 1/8 scale + key mask)
    k_softmax_ca<<<dim3(Nn, Bz * HC), 256>>>(attn, sel);

    // 19: o[b,:,hc*64:] = a[b,hc] @ v[b,:,hc*64:]  (config B: 256x64)
    mma_gemm<256,64,4,2,EPI_NONE,false><<<dim3(1, 4, Bz * HC), 256, SMB>>>(
        attn, vT, o, Nn, Nn, Nn, Dd,
        HC, (long)HC * NNt, (long)NNt, (long)ND, (long)DH * Nn, (long)ND, (long)DH,
        nullptr, zero, nullptr, nullptr, zero, zero, 0);

    // 20: out = x + gamma * (o @ caWp)
    mma_gemm<128,128,2,4,EPI_RESID,false><<<dim3(2, 64, 1), 256, SMA>>>(
        o, caWpT, out, Dd, Dd, Dd, Dd,
        1, zero, zero, zero, zero, zero, zero,
        x, zero, gamma, nullptr, zero, zero, 0);
}

// round 4
// speedup vs baseline: 2.1800x; 1.0822x over previous
#include <cuda_runtime.h>
#include <cuda_bf16.h>
#include <math.h>
#include <stdint.h>

// Problem constants
#define Bz 8
#define Nn 1024
#define Dd 256
#define Hh 8
#define HC 4
#define DH 64
#define HD 2048                 // Hh*Dd
#define ND (Nn*Dd)              // 262144
#define NNt ((size_t)Nn*Nn)     // 1048576

// ---------------- scratch (device globals) ----------------
__device__ float g_posq[Bz*Dd];
__device__ float g_w[Bz*Dd];
__device__ float g_sel[Bz*Nn];
__device__ float g_fa[Bz*ND];
__device__ uint8_t g_connect[(size_t)Bz*Nn*Nn];            // 8 MB (u8)
__device__ float g_Wh[(size_t)Bz*Hh*ND];
__device__ uint32_t g_WhT[(size_t)Bz*Hh*ND];               // P2 packed
__device__ float g_s1[Bz*Hh*Nn];
__device__ float g_s2[Bz*Hh*Nn];
__device__ float g_logits[(size_t)Bz*HC*Nn*Nn];            // CA logits fp32 (128 MB)
__device__ __nv_bfloat16 g_attn_bf[(size_t)Bz*Hh*Nn*Nn];   // GAT attn / CA attn (bf16)
__device__ __nv_bfloat16 g_attno_bf[(size_t)Bz*Nn*Nn];
__device__ float g_cat[(size_t)Bz*Nn*HD];
__device__ float g_Who[Bz*ND];
__device__ uint32_t g_WhoT[Bz*ND];                         // P2
__device__ float g_so1[Bz*Nn];
__device__ float g_so2[Bz*Nn];
__device__ float g_gout[Bz*ND];
__device__ float g_qx[Bz*ND];
__device__ float g_kv[Bz*ND];
__device__ float g_q[Bz*ND];
__device__ float g_k[Bz*ND];
__device__ float g_v[Bz*ND];
__device__ uint32_t g_vT[Bz*ND];                           // P2
__device__ float g_o[Bz*ND];
// transposed weights (fp32)
__device__ float g_adjWT[Dd*Dd];
__device__ float g_gatWT[Hh*Dd*Dd];
__device__ float g_WoT[HD*Dd];
__device__ float g_caWqT[Dd*Dd];
__device__ float g_caWkT[Dd*Dd];
__device__ float g_caWvT[Dd*Dd];
__device__ float g_caWpT[Dd*Dd];

// ---------------- low-level helpers ----------------
__device__ __forceinline__ uint32_t smem_u32(const void* p) {
    uint32_t a;
    asm("{ .reg .u64 t; cvta.to.shared.u64 t, %1; cvt.u32.u64 %0, t; }" : "=r"(a) : "l"(p));
    return a;
}
__device__ __forceinline__ void ldsm4(uint32_t* r, uint32_t addr) {
    asm volatile("ldmatrix.sync.aligned.m8n8.x4.shared.b16 {%0,%1,%2,%3}, [%4];"
        : "=r"(r[0]), "=r"(r[1]), "=r"(r[2]), "=r"(r[3]) : "r"(addr));
}
__device__ __forceinline__ void mma16816(float* c, const uint32_t* a, const uint32_t* b) {
    asm volatile("mma.sync.aligned.m16n8k16.row.col.f32.bf16.bf16.f32 "
        "{%0,%1,%2,%3}, {%4,%5,%6,%7}, {%8,%9}, {%0,%1,%2,%3};"
        : "+f"(c[0]), "+f"(c[1]), "+f"(c[2]), "+f"(c[3])
        : "r"(a[0]), "r"(a[1]), "r"(a[2]), "r"(a[3]), "r"(b[0]), "r"(b[1]));
}
__device__ __forceinline__ uint32_t packbf(float v0, float v1) {
    uint32_t r;
    asm("cvt.rn.bf16x2.f32 %0, %1, %2;" : "=r"(r) : "f"(v1), "f"(v0));
    return r;
}
__device__ __forceinline__ void split4(float4 v, uint2& h, uint2& l) {
    float h0 = __bfloat162float(__float2bfloat16(v.x));
    float h1 = __bfloat162float(__float2bfloat16(v.y));
    float h2 = __bfloat162float(__float2bfloat16(v.z));
    float h3 = __bfloat162float(__float2bfloat16(v.w));
    h.x = packbf(h0, h1); h.y = packbf(h2, h3);
    l.x = packbf(v.x - h0, v.y - h1);
    l.y = packbf(v.z - h2, v.w - h3);
}
// pack value as (hi bf16 | lo bf16<<16)
__device__ __forceinline__ uint32_t packP2(float v) {
    __nv_bfloat16 h = __float2bfloat16(v);
    float hf = __bfloat162float(h);
    __nv_bfloat16 l = __float2bfloat16(v - hf);
    return (uint32_t)__bfloat16_as_ushort(h) | ((uint32_t)__bfloat16_as_ushort(l) << 16);
}

// ---------------- merged transpose kernel (all 7 weights, fp32) ----------------
__device__ __forceinline__ void tile_transpose(const float* s, float* d, int R, int C,
                                               int bx, int by, int tx, int ty, float (*t)[33])
{
    #pragma unroll
    for (int i = 0; i < 32; i += 8)
        t[ty + i][tx] = s[(size_t)(by + ty + i) * C + bx + tx];
    __syncthreads();
    #pragma unroll
    for (int i = 0; i < 32; i += 8)
        d[(size_t)(bx + ty + i) * R + by + tx] = t[tx][ty + i];
}
__global__ void k_transpose_all(const float* adjW, float* adjWT,
                                const float* caWq, float* caWqT,
                                const float* caWk, float* caWkT,
                                const float* caWv, float* caWvT,
                                const float* caWp, float* caWpT,
                                const float* gatW, float* gatWT,
                                const float* gatWo, float* WoT)
{
    __shared__ float t[32][33];
    int id = blockIdx.x;
    int tx = threadIdx.x, ty = threadIdx.y;
    if (id < 320) {
        const float* srcs[5] = {adjW, caWq, caWk, caWv, caWp};
        float* dsts[5] = {adjWT, caWqT, caWkT, caWvT, caWpT};
        int m = id >> 6, l = id & 63;
        tile_transpose(srcs[m], dsts[m], Dd, Dd, (l & 7) * 32, (l >> 3) * 32, tx, ty, t);
    } else if (id < 832) {
        int l = id - 320;
        int z = l >> 6; l &= 63;
        tile_transpose(gatW + (size_t)z * Dd * Dd, gatWT + (size_t)z * Dd * Dd,
                       Dd, Dd, (l & 7) * 32, (l >> 3) * 32, tx, ty, t);
    } else {
        int l = id - 832;   // gatWo: [HD, Dd] -> [Dd, HD]; 8 x-tiles, 64 y-tiles
        tile_transpose(gatWo, WoT, HD, Dd, (l & 7) * 32, (l >> 3) * 32, tx, ty, t);
    }
}

// ---------------- bf16 mma.sync NT GEMM ----------------
// C[M,N] = A[M,K] @ B[N,K]^T. KTILE=32, double-buffered, 8 warps, warp tile 64x32.
// AMODE: AF32 (fp32, split hi/lo, 3 products) | ABF16 (bf16 probs, hi only, 2 products)
// BMODE: BF32 (fp32, split in loader) | BP2 (packed hi/lo uint32, prmt unpack)
enum { EPI_NONE = 0, EPI_ELU = 1, EPI_CONNECT = 2, EPI_RESID = 3 };
enum { AF32 = 0, ABF16 = 1 };
enum { BF32 = 0, BP2 = 1 };
#define ROWB 80

template <int BM, int BN, int WM, int WN, int EPI, int AMODE, int BMODE, bool DUAL>
__global__ void __launch_bounds__(256, 1)
mma_gemm(const void* __restrict__ Av, const void* __restrict__ Bv, void* __restrict__ Cv,
         int K, int lda, int ldb, int ldc, int zInner,
         long sAb, long sAi, long sBb, long sBi, long sCb, long sCi,
         const float* __restrict__ e1, long sE1b, const float* __restrict__ e2,
         uint32_t* __restrict__ Ct, long sCtb, long sCti, int ldct)
{
    constexpr int ABYTES = BM * ROWB;
    constexpr int BBYTES = BN * ROWB;
    constexpr int APASS = BM / 32;
    constexpr int BPASS = BN / 32;
    constexpr int NAPL = (AMODE == ABF16) ? 1 : 2;   // A planes per stage

    extern __shared__ char smem[];
    const uint32_t sb = smem_u32(smem);

    const int tid = threadIdx.x;
    const int wid = tid >> 5;
    const int lane = tid & 31;

    const int z = blockIdx.z;
    const int zb = z / zInner, zi = z % zInner;
    const size_t aoff = (size_t)zb * sAb + (size_t)zi * sAi;
    const size_t boff = (size_t)zb * sBb + (size_t)zi * sBi;
    const float* Apf = (AMODE == AF32) ? ((const float*)Av + aoff) : nullptr;
    const __nv_bfloat16* Apb = (AMODE == ABF16) ? ((const __nv_bfloat16*)Av + aoff) : nullptr;
    const float* Bpf = (BMODE == BF32) ? ((const float*)Bv + boff) : nullptr;
    const uint32_t* Bpp = (BMODE == BP2) ? ((const uint32_t*)Bv + boff) : nullptr;
    float* Cp = (float*)Cv + (size_t)zb * sCb + (size_t)zi * sCi;
    uint8_t* Cp8 = (uint8_t*)Cv + (size_t)zb * sCb + (size_t)zi * sCi;
    const float* e1p = e1 ? (e1 + (size_t)zb * sE1b) : nullptr;

    const int m0 = blockIdx.y * BM;
    const int n0 = blockIdx.x * BN;

    const int lq = tid & 7;
    const int lr = tid >> 3;

    const int wid_m = wid % WM;
    const int wid_n = wid / WM;
    const int g = lane >> 3, rl = lane & 7;
    const int aRowBase = wid_m * 64 + (g & 1) * 8 + rl;
    const int aKsel = (g >> 1) * 8;
    const int bRowBase = wid_n * 32 + (g >> 1) * 8 + rl;
    const int bKsel = (g & 1) * 8;

    float acc[4][4][4] = {};
    float4 paf[APASS]; uint2 pab[APASS];
    float4 pbf[BPASS]; uint4 pbp[BPASS];

    const int nkt = K >> 5;
    const uint32_t bbase = 2 * NAPL * ABYTES;

    auto loadA = [&](int kk) {
        #pragma unroll
        for (int i = 0; i < APASS; i++) {
            if (AMODE == AF32)
                paf[i] = *reinterpret_cast<const float4*>(Apf + (size_t)(m0 + lr + 32 * i) * lda + kk + lq * 4);
            else
                pab[i] = *reinterpret_cast<const uint2*>(Apb + (size_t)(m0 + lr + 32 * i) * lda + kk + lq * 4);
        }
    };
    auto loadB = [&](int kk) {
        #pragma unroll
        for (int i = 0; i < BPASS; i++) {
            if (BMODE == BF32)
                pbf[i] = *reinterpret_cast<const float4*>(Bpf + (size_t)(n0 + lr + 32 * i) * ldb + kk + lq * 4);
            else
                pbp[i] = *reinterpret_cast<const uint4*>(Bpp + (size_t)(n0 + lr + 32 * i) * ldb + kk + lq * 4);
        }
    };
    auto storeA = [&](int stage) {
        #pragma unroll
        for (int i = 0; i < APASS; i++) {
            int off = stage * NAPL * ABYTES + (lr + 32 * i) * ROWB + lq * 8;
            if (AMODE == AF32) {
                uint2 h, l; split4(paf[i], h, l);
                *reinterpret_cast<uint2*>(smem + off) = h;
                *reinterpret_cast<uint2*>(smem + ABYTES + off) = l;
            } else {
                *reinterpret_cast<uint2*>(smem + off) = pab[i];
            }
        }
    };
    auto storeB = [&](int stage) {
        #pragma unroll
        for (int i = 0; i < BPASS; i++) {
            int off = bbase + stage * 2 * BBYTES + (lr + 32 * i) * ROWB + lq * 8;
            uint2 h, l;
            if (BMODE == BF32) {
                split4(pbf[i], h, l);
            } else {
                h.x = __byte_perm(pbp[i].x, pbp[i].y, 0x5410);
                h.y = __byte_perm(pbp[i].z, pbp[i].w, 0x5410);
                l.x = __byte_perm(pbp[i].x, pbp[i].y, 0x7632);
                l.y = __byte_perm(pbp[i].z, pbp[i].w, 0x7632);
            }
            *reinterpret_cast<uint2*>(smem + off) = h;
            *reinterpret_cast<uint2*>(smem + BBYTES + off) = l;
        }
    };

    // prologue
    loadA(0); loadB(0);
    storeA(0); storeB(0);
    __syncthreads();

    for (int kt = 0; kt < nkt; kt++) {
        const int stage = kt & 1;
        const bool more = (kt + 1 < nkt);
        if (more) { loadA((kt + 1) << 5); loadB((kt + 1) << 5); }

        const uint32_t sAhi = sb + stage * NAPL * ABYTES;
        const uint32_t sAlo = sAhi + ABYTES;
        const uint32_t sBhi = sb + bbase + stage * 2 * BBYTES;
        const uint32_t sBlo = sBhi + BBYTES;

        #pragma unroll
        for (int j = 0; j < 2; j++) {
            const int kb = j * 16;
            uint32_t a[4][4], bh[4][2], bl[4][2];
            #pragma unroll
            for (int im = 0; im < 4; im++)
                ldsm4(a[im], sAhi + (uint32_t)((aRowBase + im * 16) * ROWB + (kb + aKsel) * 2));
            #pragma unroll
            for (int i2 = 0; i2 < 2; i2++) {
                uint32_t t[4];
                ldsm4(t, sBhi + (uint32_t)((bRowBase + i2 * 16) * ROWB + (kb + bKsel) * 2));
                bh[2 * i2][0] = t[0]; bh[2 * i2][1] = t[1];
                bh[2 * i2 + 1][0] = t[2]; bh[2 * i2 + 1][1] = t[3];
            }
            #pragma unroll
            for (int im = 0; im < 4; im++)
                #pragma unroll
                for (int in = 0; in < 4; in++)
                    mma16816(acc[im][in], a[im], bh[in]);           // Ah*Bh
            #pragma unroll
            for (int i2 = 0; i2 < 2; i2++) {
                uint32_t t[4];
                ldsm4(t, sBlo + (uint32_t)((bRowBase + i2 * 16) * ROWB + (kb + bKsel) * 2));
                bl[2 * i2][0] = t[0]; bl[2 * i2][1] = t[1];
                bl[2 * i2 + 1][0] = t[2]; bl[2 * i2 + 1][1] = t[3];
            }
            #pragma unroll
            for (int im = 0; im < 4; im++)
                #pragma unroll
                for (int in = 0; in < 4; in++)
                    mma16816(acc[im][in], a[im], bl[in]);           // Ah*Bl
            if (AMODE == AF32) {
                #pragma unroll
                for (int im = 0; im < 4; im++)
                    ldsm4(a[im], sAlo + (uint32_t)((aRowBase + im * 16) * ROWB + (kb + aKsel) * 2));
                #pragma unroll
                for (int im = 0; im < 4; im++)
                    #pragma unroll
                    for (int in = 0; in < 4; in++)
                        mma16816(acc[im][in], a[im], bh[in]);       // Al*Bh
            }
        }

        if (more) { storeA(stage ^ 1); storeB(stage ^ 1); }
        __syncthreads();
    }

    // epilogue
    const int mw = m0 + wid_m * 64;
    const int nw = n0 + wid_n * 32;
    #pragma unroll
    for (int im = 0; im < 4; im++) {
        const int row = mw + im * 16 + (lane >> 2);
        const float sr0 = (EPI == EPI_CONNECT) ? e1p[row] : 0.f;
        const float sr1 = (EPI == EPI_CONNECT) ? e1p[row + 8] : 0.f;
        #pragma unroll
        for (int in = 0; in < 4; in++) {
            const int col = nw + in * 8 + (lane & 3) * 2;
            float v00 = acc[im][in][0], v01 = acc[im][in][1];
            float v10 = acc[im][in][2], v11 = acc[im][in][3];
            if (EPI == EPI_ELU) {
                v00 = v00 > 0.f ? v00 : expm1f(v00);
                v01 = v01 > 0.f ? v01 : expm1f(v01);
                v10 = v10 > 0.f ? v10 : expm1f(v10);
                v11 = v11 > 0.f ? v11 : expm1f(v11);
            } else if (EPI == EPI_RESID) {
                const float g0 = e2[col], g1 = e2[col + 1];
                const size_t r0 = (size_t)row * ldc + col;
                const size_t r1 = (size_t)(row + 8) * ldc + col;
                v00 = e1p[r0] + g0 * v00; v01 = e1p[r0 + 1] + g1 * v01;
                v10 = e1p[r1] + g0 * v10; v11 = e1p[r1 + 1] + g1 * v11;
            }
            if (EPI == EPI_CONNECT) {
                const float sc0 = e1p[col], sc1 = e1p[col + 1];
                uchar2 c0, c1;
                c0.x = (v00 > 0.f && sr0 > 0.5f && sc0 > 0.5f) ? 1 : 0;
                c0.y = (v01 > 0.f && sr0 > 0.5f && sc1 > 0.5f) ? 1 : 0;
                c1.x = (v10 > 0.f && sr1 > 0.5f && sc0 > 0.5f) ? 1 : 0;
                c1.y = (v11 > 0.f && sr1 > 0.5f && sc1 > 0.5f) ? 1 : 0;
                *reinterpret_cast<uchar2*>(Cp8 + (size_t)row * ldc + col) = c0;
                *reinterpret_cast<uchar2*>(Cp8 + (size_t)(row + 8) * ldc + col) = c1;
            } else {
                *reinterpret_cast<float2*>(Cp + (size_t)row * ldc + col) = make_float2(v00, v01);
                *reinterpret_cast<float2*>(Cp + (size_t)(row + 8) * ldc + col) = make_float2(v10, v11);
            }
            if (DUAL) {
                uint32_t* Ctp = Ct + (size_t)zb * sCtb + (size_t)zi * sCti;
                Ctp[(size_t)col * ldct + row] = packP2(v00);
                Ctp[(size_t)(col + 1) * ldct + row] = packP2(v01);
                Ctp[(size_t)col * ldct + row + 8] = packP2(v10);
                Ctp[(size_t)(col + 1) * ldct + row + 8] = packP2(v11);
            }
        }
    }
}

// ---------------- auxiliary kernels ----------------
__global__ void k_posquery(const float* __restrict__ x, const int* __restrict__ mask,
                           float* __restrict__ pq)
{
    int b = blockIdx.x, d = threadIdx.x;
    float s = 0.f, cnt = 0.f;
    for (int n = 0; n < Nn; n++) {
        int m = mask[b * Nn + n];
        if (m == 1) { s += x[((size_t)b * Nn + n) * Dd + d]; cnt += 1.f; }
    }
    pq[b * Dd + d] = s / fmaxf(cnt, 1.f);
}

__global__ void k_simvec(const float* __restrict__ Wx, const float* __restrict__ Wq,
                         const float* __restrict__ pq, float* __restrict__ w)
{
    __shared__ float spq[Dd];
    __shared__ float qs[Dd];
    int b = blockIdx.x, t = threadIdx.x;
    spq[t] = pq[b * Dd + t];
    __syncthreads();
    float a = 0.f;
    for (int i = 0; i < Dd; i++) a += spq[i] * Wq[i * Dd + t];
    qs[t] = a;
    __syncthreads();
    float a2 = 0.f;
    for (int j = 0; j < Dd; j++) a2 += Wx[t * Dd + j] * qs[j];
    w[b * Dd + t] = a2;
}

__global__ void k_possim(const float* __restrict__ x, const float* __restrict__ w,
                         float* __restrict__ possim_out, float* __restrict__ sel)
{
    int row = blockIdx.x * 8 + (threadIdx.x >> 5);
    int lane = threadIdx.x & 31;
    int b = row / Nn;
    float s = 0.f;
    for (int e = lane; e < Dd; e += 32) s += x[(size_t)row * Dd + e] * w[b * Dd + e];
    #pragma unroll
    for (int o = 16; o; o >>= 1) s += __shfl_xor_sync(0xffffffffu, s, o);
    if (lane == 0) {
        float p = 1.f / (1.f + expf(-s * 0.0625f));
        possim_out[row] = p;
        sel[row] = (p > 0.97f) ? 1.f : 0.f;
    }
}

__global__ void k_dot2(const float* __restrict__ rows, const float* __restrict__ a1,
                       const float* __restrict__ a2, float* __restrict__ s1,
                       float* __restrict__ s2, int nheads)
{
    int row = blockIdx.x * 8 + (threadIdx.x >> 5);
    int lane = threadIdx.x & 31;
    int head = (row / Nn) % nheads;
    const float* rp = rows + (size_t)row * Dd;
    const float* a1p = a1 + head * Dd;
    const float* a2p = a2 + head * Dd;
    float u = 0.f, v = 0.f;
    for (int e = lane; e < Dd; e += 32) {
        float rv = rp[e];
        u += rv * a1p[e];
        v += rv * a2p[e];
    }
    #pragma unroll
    for (int o = 16; o; o >>= 1) {
        u += __shfl_xor_sync(0xffffffffu, u, o);
        v += __shfl_xor_sync(0xffffffffu, v, o);
    }
    if (lane == 0) { s1[row] = u; s2[row] = v; }
}

// GAT masked softmax -> bf16 output
__global__ void k_softmax_gat(const float* __restrict__ s1, const float* __restrict__ s2,
                              const uint8_t* __restrict__ connect, __nv_bfloat16* __restrict__ attn,
                              int nheads)
{
    __shared__ float red[256];
    int i = blockIdx.x;
    int z = blockIdx.y;
    int b = z / nheads;
    const uint8_t* con = connect + (size_t)b * NNt + (size_t)i * Nn;
    const float* s2p = s2 + (size_t)z * Nn;
    float s1v = s1[(size_t)z * Nn + i];
    int t = threadIdx.x;
    float v[4];
    float mx = -INFINITY;
    #pragma unroll
    for (int k = 0; k < 4; k++) {
        int j = t + k * 256;
        float e = s1v + s2p[j];
        e = (e >= 0.f) ? e : 0.2f * e;
        v[k] = con[j] ? e : -9.0e15f;
        mx = fmaxf(mx, v[k]);
    }
    red[t] = mx; __syncthreads();
    for (int s = 128; s > 0; s >>= 1) { if (t < s) red[t] = fmaxf(red[t], red[t + s]); __syncthreads(); }
    mx = red[0]; __syncthreads();
    float sum = 0.f;
    #pragma unroll
    for (int k = 0; k < 4; k++) { v[k] = expf(v[k] - mx); sum += v[k]; }
    red[t] = sum; __syncthreads();
    for (int s = 128; s > 0; s >>= 1) { if (t < s) red[t] += red[t + s]; __syncthreads(); }
    float inv = 1.f / red[0];
    __nv_bfloat16* out = attn + (size_t)z * NNt + (size_t)i * Nn;
    #pragma unroll
    for (int k = 0; k < 4; k++) out[t + k * 256] = __float2bfloat16(v[k] * inv);
}

// CA masked softmax: fp32 logits in, bf16 out, scale 0.125
__global__ void k_softmax_ca(const float* __restrict__ logits, const float* __restrict__ sel,
                             __nv_bfloat16* __restrict__ attn)
{
    __shared__ float red[256];
    int i = blockIdx.x;
    int z = blockIdx.y;
    int b = z / HC;
    const float* row = logits + (size_t)z * NNt + (size_t)i * Nn;
    const float* sp = sel + b * Nn;
    int t = threadIdx.x;
    float v[4];
    float mx = -INFINITY;
    #pragma unroll
    for (int k = 0; k < 4; k++) {
        int j = t + k * 256;
        v[k] = (sp[j] > 0.5f) ? row[j] * 0.125f : -1.0e9f;
        mx = fmaxf(mx, v[k]);
    }
    red[t] = mx; __syncthreads();
    for (int s = 128; s > 0; s >>= 1) { if (t < s) red[t] = fmaxf(red[t], red[t + s]); __syncthreads(); }
    mx = red[0]; __syncthreads();
    float sum = 0.f;
    #pragma unroll
    for (int k = 0; k < 4; k++) { v[k] = expf(v[k] - mx); sum += v[k]; }
    red[t] = sum; __syncthreads();
    for (int s = 128; s > 0; s >>= 1) { if (t < s) red[t] += red[t + s]; __syncthreads(); }
    float inv = 1.f / red[0];
    __nv_bfloat16* out = attn + (size_t)z * NNt + (size_t)i * Nn;
    #pragma unroll
    for (int k = 0; k < 4; k++) out[t + k * 256] = __float2bfloat16(v[k] * inv);
}

__global__ void k_ln(const float* __restrict__ in, const float* __restrict__ g,
                     const float* __restrict__ bb, float* __restrict__ out)
{
    int row = blockIdx.x * 8 + (threadIdx.x >> 5);
    int lane = threadIdx.x & 31;
    size_t base = (size_t)row * Dd;
    float vbuf[8];
    float s = 0.f, sq = 0.f;
    #pragma unroll
    for (int k = 0; k < 8; k++) {
        float x = in[base + lane + k * 32];
        vbuf[k] = x; s += x; sq += x * x;
    }
    #pragma unroll
    for (int o = 16; o; o >>= 1) {
        s += __shfl_xor_sync(0xffffffffu, s, o);
        sq += __shfl_xor_sync(0xffffffffu, sq, o);
    }
    float mean = s * (1.f / Dd);
    float var = sq * (1.f / Dd) - mean * mean;
    float rstd = rsqrtf(var + 1e-5f);
    #pragma unroll
    for (int k = 0; k < 8; k++) {
        int d = lane + k * 32;
        out[base + d] = (vbuf[k] - mean) * rstd * g[d] + bb[d];
    }
}

__global__ void k_qfull_ln(const float* __restrict__ gout, const float* __restrict__ pe,
                           const float* __restrict__ sel, const float* __restrict__ g,
                           const float* __restrict__ bb, float* __restrict__ out)
{
    int row = blockIdx.x * 8 + (threadIdx.x >> 5);
    int lane = threadIdx.x & 31;
    int n = row % Nn;
    size_t base = (size_t)row * Dd;
    float selv = sel[row];
    float vbuf[8];
    float s = 0.f, sq = 0.f;
    #pragma unroll
    for (int k = 0; k < 8; k++) {
        int d = lane + k * 32;
        float x = (selv > 0.5f) ? (gout[base + d] + pe[(size_t)n * Dd + d]) : 0.f;
        vbuf[k] = x; s += x; sq += x * x;
    }
    #pragma unroll
    for (int o = 16; o; o >>= 1) {
        s += __shfl_xor_sync(0xffffffffu, s, o);
        sq += __shfl_xor_sync(0xffffffffu, sq, o);
    }
    float mean = s * (1.f / Dd);
    float var = sq * (1.f / Dd) - mean * mean;
    float rstd = rsqrtf(var + 1e-5f);
    #pragma unroll
    for (int k = 0; k < 8; k++) {
        int d = lane + k * 32;
        out[base + d] = (vbuf[k] - mean) * rstd * g[d] + bb[d];
    }
}

// ---------------- launch ----------------
#define GETSYM(p, T, s) do { void* _t; cudaGetSymbolAddress(&_t, s); p = (T*)_t; } while (0)
#define SMEMSZ(BM, BN, NAPL) (2 * (NAPL) * (BM) * ROWB + 4 * (BN) * ROWB)

extern "C" void kernel_launch(void* const* d_in, const int* in_sizes, int n_in,
                              void* d_out, int out_size)
{
    const float* x      = (const float*)d_in[0];
    const int*   mask   = (const int*)  d_in[1];
    const float* pe     = (const float*)d_in[2];
    const float* simWx  = (const float*)d_in[3];
    const float* simWq  = (const float*)d_in[4];
    const float* adjW   = (const float*)d_in[5];
    const float* gatW   = (const float*)d_in[6];
    const float* gatA1  = (const float*)d_in[7];
    const float* gatA2  = (const float*)d_in[8];
    const float* gatWo  = (const float*)d_in[9];
    const float* gatAo1 = (const float*)d_in[10];
    const float* gatAo2 = (const float*)d_in[11];
    const float* ln3g   = (const float*)d_in[12];
    const float* ln3b   = (const float*)d_in[13];
    const float* ln4g   = (const float*)d_in[14];
    const float* ln4b   = (const float*)d_in[15];
    const float* caWq   = (const float*)d_in[16];
    const float* caWk   = (const float*)d_in[17];
    const float* caWv   = (const float*)d_in[18];
    const float* caWp   = (const float*)d_in[19];
    const float* gamma  = (const float*)d_in[20];
    (void)in_sizes; (void)n_in; (void)out_size;

    float* out = (float*)d_out;
    float* possim_out = out + (size_t)Bz * Nn * Dd;

    float *posq, *w, *sel, *fa, *Wh, *s1, *s2, *logits, *cat, *Who;
    float *so1, *so2, *gout, *qx, *kv, *q, *k, *v, *o;
    uint8_t* connect;
    uint32_t *WhT, *WhoT, *vT;
    __nv_bfloat16 *attn_bf, *attno_bf;
    float *adjWT, *gatWT, *WoT, *caWqT, *caWkT, *caWvT, *caWpT;
    GETSYM(posq, float, g_posq);   GETSYM(w, float, g_w);       GETSYM(sel, float, g_sel);
    GETSYM(fa, float, g_fa);       GETSYM(connect, uint8_t, g_connect);
    GETSYM(Wh, float, g_Wh);       GETSYM(WhT, uint32_t, g_WhT);
    GETSYM(s1, float, g_s1);       GETSYM(s2, float, g_s2);
    GETSYM(logits, float, g_logits);
    GETSYM(attn_bf, __nv_bfloat16, g_attn_bf);
    GETSYM(attno_bf, __nv_bfloat16, g_attno_bf);
    GETSYM(cat, float, g_cat);
    GETSYM(Who, float, g_Who);     GETSYM(WhoT, uint32_t, g_WhoT);
    GETSYM(so1, float, g_so1);     GETSYM(so2, float, g_so2);
    GETSYM(gout, float, g_gout);   GETSYM(qx, float, g_qx);     GETSYM(kv, float, g_kv);
    GETSYM(q, float, g_q);         GETSYM(k, float, g_k);       GETSYM(v, float, g_v);
    GETSYM(vT, uint32_t, g_vT);    GETSYM(o, float, g_o);
    GETSYM(adjWT, float, g_adjWT); GETSYM(gatWT, float, g_gatWT); GETSYM(WoT, float, g_WoT);
    GETSYM(caWqT, float, g_caWqT); GETSYM(caWkT, float, g_caWkT);
    GETSYM(caWvT, float, g_caWvT); GETSYM(caWpT, float, g_caWpT);

    const int SM_FF  = SMEMSZ(128, 128, 2);   // AF32 128x128
    const int SM_BP  = SMEMSZ(128, 128, 1);   // ABF16 128x128
    const int SM_BP2 = SMEMSZ(256, 64, 1);    // ABF16 256x64
    cudaFuncSetAttribute(mma_gemm<128,128,2,4,EPI_NONE,   AF32, BF32,false>, cudaFuncAttributeMaxDynamicSharedMemorySize, SM_FF);
    cudaFuncSetAttribute(mma_gemm<128,128,2,4,EPI_NONE,   AF32, BF32,true >, cudaFuncAttributeMaxDynamicSharedMemorySize, SM_FF);
    cudaFuncSetAttribute(mma_gemm<128,128,2,4,EPI_CONNECT,AF32, BF32,false>, cudaFuncAttributeMaxDynamicSharedMemorySize, SM_FF);
    cudaFuncSetAttribute(mma_gemm<128,128,2,4,EPI_RESID,  AF32, BF32,false>, cudaFuncAttributeMaxDynamicSharedMemorySize, SM_FF);
    cudaFuncSetAttribute(mma_gemm<128,128,2,4,EPI_ELU,    ABF16,BP2, false>, cudaFuncAttributeMaxDynamicSharedMemorySize, SM_BP);
    cudaFuncSetAttribute(mma_gemm<256,64, 4,2,EPI_NONE,   ABF16,BP2, false>, cudaFuncAttributeMaxDynamicSharedMemorySize, SM_BP2);

    const long zero = 0;

    // 0: all weight transposes in one launch
    k_transpose_all<<<1344, dim3(32, 8)>>>(adjW, adjWT, caWq, caWqT, caWk, caWkT,
                                           caWv, caWvT, caWp, caWpT, gatW, gatWT, gatWo, WoT);

    // 1-3: selection path
    k_posquery<<<Bz, 256>>>(x, mask, posq);
    k_simvec<<<Bz, 256>>>(simWx, simWq, posq, w);
    k_possim<<<Bz * Nn / 8, 256>>>(x, w, possim_out, sel);

    // 4: fa = x @ adjW
    mma_gemm<128,128,2,4,EPI_NONE,AF32,BF32,false><<<dim3(2, 64, 1), 256, SM_FF>>>(
        x, adjWT, fa, Dd, Dd, Dd, Dd,
        1, zero, zero, zero, zero, zero, zero,
        nullptr, zero, nullptr, nullptr, zero, zero, 0);

    // 5: connect (u8) = (fa fa^T > 0) & sel_i & sel_j
    mma_gemm<128,128,2,4,EPI_CONNECT,AF32,BF32,false><<<dim3(8, 8, Bz), 256, SM_FF>>>(
        fa, fa, connect, Dd, Dd, Dd, Nn,
        1, (long)ND, zero, (long)ND, zero, (long)NNt, zero,
        sel, (long)Nn, nullptr, nullptr, zero, zero, 0);

    // 6: Wh = x @ gatW[h]; dual-write WhT (P2)
    mma_gemm<128,128,2,4,EPI_NONE,AF32,BF32,true><<<dim3(2, 8, Bz * Hh), 256, SM_FF>>>(
        x, gatWT, Wh, Dd, Dd, Dd, Dd,
        Hh, (long)ND, zero, zero, (long)Dd * Dd, (long)Hh * ND, (long)ND,
        nullptr, zero, nullptr, WhT, (long)Hh * ND, (long)ND, Nn);

    // 7: s1/s2
    k_dot2<<<Bz * Hh * Nn / 8, 256>>>(Wh, gatA1, gatA2, s1, s2, Hh);

    // 8: GAT softmax -> bf16
    k_softmax_gat<<<dim3(Nn, Bz * Hh), 256>>>(s1, s2, connect, attn_bf, Hh);

    // 9: cat = elu( attn @ Wh )   [A bf16, B P2, 2-product]
    mma_gemm<128,128,2,4,EPI_ELU,ABF16,BP2,false><<<dim3(2, 8, Bz * Hh), 256, SM_BP>>>(
        attn_bf, WhT, cat, Nn, Nn, Nn, HD,
        Hh, (long)Hh * NNt, (long)NNt, (long)Hh * ND, (long)ND, (long)Nn * HD, (long)Dd,
        nullptr, zero, nullptr, nullptr, zero, zero, 0);

    // 10: Who = cat @ gatWo; dual-write WhoT (P2)
    mma_gemm<128,128,2,4,EPI_NONE,AF32,BF32,true><<<dim3(2, 8, Bz), 256, SM_FF>>>(
        cat, WoT, Who, HD, HD, HD, Dd,
        1, (long)Nn * HD, zero, zero, zero, (long)ND, zero,
        nullptr, zero, nullptr, WhoT, (long)ND, zero, Nn);

    // 11: so1/so2
    k_dot2<<<Bz * Nn / 8, 256>>>(Who, gatAo1, gatAo2, so1, so2, 1);

    // 12: out-layer softmax -> bf16
    k_softmax_gat<<<dim3(Nn, Bz), 256>>>(so1, so2, connect, attno_bf, 1);

    // 13: gout = elu( attn_o @ Who )   [2-product]
    mma_gemm<128,128,2,4,EPI_ELU,ABF16,BP2,false><<<dim3(2, 8, Bz), 256, SM_BP>>>(
        attno_bf, WhoT, gout, Nn, Nn, Nn, Dd,
        1, (long)NNt, zero, (long)ND, zero, (long)ND, zero,
        nullptr, zero, nullptr, nullptr, zero, zero, 0);

    // 14-15: LayerNorms
    k_ln<<<Bz * Nn / 8, 256>>>(x, ln3g, ln3b, qx);
    k_qfull_ln<<<Bz * Nn / 8, 256>>>(gout, pe, sel, ln4g, ln4b, kv);

    // 16: q/k/v projections; v dual-writes vT (P2)
    mma_gemm<128,128,2,4,EPI_NONE,AF32,BF32,false><<<dim3(2, 64, 1), 256, SM_FF>>>(
        qx, caWqT, q, Dd, Dd, Dd, Dd,
        1, zero, zero, zero, zero, zero, zero,
        nullptr, zero, nullptr, nullptr, zero, zero, 0);
    mma_gemm<128,128,2,4,EPI_NONE,AF32,BF32,false><<<dim3(2, 64, 1), 256, SM_FF>>>(
        kv, caWkT, k, Dd, Dd, Dd, Dd,
        1, zero, zero, zero, zero, zero, zero,
        nullptr, zero, nullptr, nullptr, zero, zero, 0);
    mma_gemm<128,128,2,4,EPI_NONE,AF32,BF32,true><<<dim3(2, 8, Bz), 256, SM_FF>>>(
        kv, caWvT, v, Dd, Dd, Dd, Dd,
        1, (long)ND, zero, zero, zero, (long)ND, zero,
        nullptr, zero, nullptr, vT, (long)ND, zero, Nn);

    // 17: CA logits (fp32)
    mma_gemm<128,128,2,4,EPI_NONE,AF32,BF32,false><<<dim3(8, 8, Bz * HC), 256, SM_FF>>>(
        q, k, logits, DH, Dd, Dd, Nn,
        HC, (long)ND, (long)DH, (long)ND, (long)DH, (long)HC * NNt, (long)NNt,
        nullptr, zero, nullptr, nullptr, zero, zero, 0);

    // 18: CA softmax -> bf16 (reuse attn_bf)
    k_softmax_ca<<<dim3(Nn, Bz * HC), 256>>>(logits, sel, attn_bf);

    // 19: o = a @ v   [2-product, 256x64 tiles]
    mma_gemm<256,64,4,2,EPI_NONE,ABF16,BP2,false><<<dim3(1, 4, Bz * HC), 256, SM_BP2>>>(
        attn_bf, vT, o, Nn, Nn, Nn, Dd,
        HC, (long)HC * NNt, (long)NNt, (long)ND, (long)DH * Nn, (long)ND, (long)DH,
        nullptr, zero, nullptr, nullptr, zero, zero, 0);

    // 20: out = x + gamma * (o @ caWp)
    mma_gemm<128,128,2,4,EPI_RESID,AF32,BF32,false><<<dim3(2, 64, 1), 256, SM_FF>>>(
        o, caWpT, out, Dd, Dd, Dd, Dd,
        1, zero, zero, zero, zero, zero, zero,
        x, zero, gamma, nullptr, zero, zero, 0);
}